// round 1
// baseline (speedup 1.0000x reference)
#include <cuda_runtime.h>
#include <cuda_bf16.h>

// GeometricHyperConnections — fused, HBM-bound.
// b=4, s=4, T=2048, d=2048, k=4 (fixed by setup_inputs).
// One CTA per (b,t) token; 256 threads; float4 streaming.

#define T_DIM 2048
#define D_DIM 2048
#define D4    512         // D_DIM/4
#define B_DIM 4
#define S_DIM 4
#define K_DIM 4
#define TAU   0.05f
#define LOGM  (-1.3862943611198906f)   // -log(4)
#define RMSEPS 1e-6f

__global__ void __launch_bounds__(256)
ghc_kernel(const float* __restrict__ resid,
           const float* __restrict__ branch,
           const float* __restrict__ rmsw,
           const float* __restrict__ projW,
           const float* __restrict__ log_sigma,
           const float* __restrict__ pre_logits,
           const float* __restrict__ post_logits,
           float* __restrict__ out_bi,     // (B,T,D)
           float* __restrict__ out_mix)    // (B*S,T,D)
{
    __shared__ float red[8][20];
    __shared__ float fin[20];
    __shared__ float coords[16];
    __shared__ float Hs[16];     // Hs[s*4+u]
    __shared__ float Hpre[4], Hpost[4];

    const int tid = threadIdx.x;
    const int m   = blockIdx.x;
    const int bi  = m >> 11;          // m / T_DIM
    const int t   = m & (T_DIM - 1);

    const float4* R4 = (const float4*)resid;
    const float4* W4 = (const float4*)rmsw;
    const float4* P4 = (const float4*)projW;

    size_t rbase[S_DIM];
#pragma unroll
    for (int si = 0; si < S_DIM; si++)
        rbase[si] = ((size_t)(bi * S_DIM + si) * T_DIM + t) * D4;

    // ---------------- Pass 1: stats (sumsq + weighted dots with proj_W) ----
    float sumsq[S_DIM];
    float dot[S_DIM][K_DIM];
#pragma unroll
    for (int si = 0; si < S_DIM; si++) {
        sumsq[si] = 0.f;
#pragma unroll
        for (int k = 0; k < K_DIM; k++) dot[si][k] = 0.f;
    }

#pragma unroll
    for (int j = 0; j < 2; j++) {
        const int c = tid + j * 256;
        const float4 w = W4[c];
        float4 p[K_DIM];
#pragma unroll
        for (int k = 0; k < K_DIM; k++) p[k] = P4[k * D4 + c];
#pragma unroll
        for (int si = 0; si < S_DIM; si++) {
            const float4 r = R4[rbase[si] + c];
            sumsq[si] += r.x*r.x + r.y*r.y + r.z*r.z + r.w*r.w;
            const float rwx = r.x*w.x, rwy = r.y*w.y, rwz = r.z*w.z, rww = r.w*w.w;
#pragma unroll
            for (int k = 0; k < K_DIM; k++)
                dot[si][k] += rwx*p[k].x + rwy*p[k].y + rwz*p[k].z + rww*p[k].w;
        }
    }

    // ---------------- Block reduction of 20 values ------------------------
    float vals[20];
#pragma unroll
    for (int si = 0; si < S_DIM; si++) {
        vals[si] = sumsq[si];
#pragma unroll
        for (int k = 0; k < K_DIM; k++) vals[4 + si * 4 + k] = dot[si][k];
    }
#pragma unroll
    for (int v = 0; v < 20; v++) {
        float x = vals[v];
#pragma unroll
        for (int off = 16; off; off >>= 1)
            x += __shfl_xor_sync(0xffffffffu, x, off);
        vals[v] = x;
    }
    const int warp = tid >> 5, lane = tid & 31;
    if (lane == 0) {
#pragma unroll
        for (int v = 0; v < 20; v++) red[warp][v] = vals[v];
    }
    __syncthreads();

    // ---------------- Warp 0: coords, Sinkhorn, softmaxes -----------------
    if (warp == 0) {
        if (lane < 20) {
            float a = 0.f;
#pragma unroll
            for (int w = 0; w < 8; w++) a += red[w][lane];
            fin[lane] = a;
        }
        __syncwarp();
        if (lane < 16) {
            const int si = lane >> 2;
            const float scale = rsqrtf(fin[si] * (1.f / (float)D_DIM) + RMSEPS);
            coords[lane] = scale * fin[4 + lane];   // fin[4 + si*4 + k]
        }
        __syncwarp();
        if (lane < 16) {
            const int i = lane >> 2, jj = lane & 3;
            float ds = 0.f;
#pragma unroll
            for (int k = 0; k < K_DIM; k++) {
                const float df = coords[i * 4 + k] - coords[jj * 4 + k];
                ds += df * df;
            }
            const float sigma_sq = __expf(2.f * log_sigma[0]);
            const float Z = -ds / (2.f * sigma_sq * TAU);

            float u = 0.f, v = 0.f;
            const unsigned M = 0x0000ffffu;
#pragma unroll
            for (int it = 0; it < 10; it++) {
                // u_i = logm - lse_j(Z + v_j)   (reduce within quad: xor 1,2)
                float t0 = Z + v;
                float mx = t0;
                mx = fmaxf(mx, __shfl_xor_sync(M, mx, 1));
                mx = fmaxf(mx, __shfl_xor_sync(M, mx, 2));
                float p = __expf(t0 - mx);
                p += __shfl_xor_sync(M, p, 1);
                p += __shfl_xor_sync(M, p, 2);
                u = LOGM - (mx + __logf(p));
                // v_j = logm - lse_i(Z + u_i)   (reduce across quads: xor 4,8)
                float t1 = Z + u;
                mx = t1;
                mx = fmaxf(mx, __shfl_xor_sync(M, mx, 4));
                mx = fmaxf(mx, __shfl_xor_sync(M, mx, 8));
                p = __expf(t1 - mx);
                p += __shfl_xor_sync(M, p, 4);
                p += __shfl_xor_sync(M, p, 8);
                v = LOGM - (mx + __logf(p));
            }
            Hs[lane] = __expf(Z + u + v) * (float)S_DIM;
        }
        if (lane == 0) {
            // softmax of H_pre_logits and H_post_logits (4 each)
            float l[4], mx, e[4], sm;
#pragma unroll
            for (int i = 0; i < 4; i++) l[i] = pre_logits[i];
            mx = fmaxf(fmaxf(l[0], l[1]), fmaxf(l[2], l[3]));
            sm = 0.f;
#pragma unroll
            for (int i = 0; i < 4; i++) { e[i] = __expf(l[i] - mx); sm += e[i]; }
#pragma unroll
            for (int i = 0; i < 4; i++) Hpre[i] = e[i] / sm;
#pragma unroll
            for (int i = 0; i < 4; i++) l[i] = post_logits[i];
            mx = fmaxf(fmaxf(l[0], l[1]), fmaxf(l[2], l[3]));
            sm = 0.f;
#pragma unroll
            for (int i = 0; i < 4; i++) { e[i] = __expf(l[i] - mx); sm += e[i]; }
#pragma unroll
            for (int i = 0; i < 4; i++) Hpost[i] = e[i] / sm;
        }
    }
    __syncthreads();

    // ---------------- Pass 2: mixing + outputs ----------------------------
    float H[16], hp[4], hq[4];
#pragma unroll
    for (int i = 0; i < 16; i++) H[i] = Hs[i];
#pragma unroll
    for (int i = 0; i < 4; i++) { hp[i] = Hpre[i]; hq[i] = Hpost[i]; }

    const float4* BO4 = (const float4*)branch;
    float4* OBI = (float4*)out_bi;
    float4* OMX = (float4*)out_mix;
    const size_t bbase = ((size_t)bi * T_DIM + t) * D4;

#pragma unroll
    for (int j = 0; j < 2; j++) {
        const int c = tid + j * 256;
        const float4 r0 = R4[rbase[0] + c];
        const float4 r1 = R4[rbase[1] + c];
        const float4 r2 = R4[rbase[2] + c];
        const float4 r3 = R4[rbase[3] + c];
        const float4 bo = BO4[bbase + c];

        float4 o;
        o.x = hp[0]*r0.x + hp[1]*r1.x + hp[2]*r2.x + hp[3]*r3.x;
        o.y = hp[0]*r0.y + hp[1]*r1.y + hp[2]*r2.y + hp[3]*r3.y;
        o.z = hp[0]*r0.z + hp[1]*r1.z + hp[2]*r2.z + hp[3]*r3.z;
        o.w = hp[0]*r0.w + hp[1]*r1.w + hp[2]*r2.w + hp[3]*r3.w;
        OBI[bbase + c] = o;

#pragma unroll
        for (int u = 0; u < 4; u++) {
            const float h0 = H[0 * 4 + u], h1 = H[1 * 4 + u],
                        h2 = H[2 * 4 + u], h3 = H[3 * 4 + u], hb = hq[u];
            float4 q;
            q.x = hb*bo.x + h0*r0.x + h1*r1.x + h2*r2.x + h3*r3.x;
            q.y = hb*bo.y + h0*r0.y + h1*r1.y + h2*r2.y + h3*r3.y;
            q.z = hb*bo.z + h0*r0.z + h1*r1.z + h2*r2.z + h3*r3.z;
            q.w = hb*bo.w + h0*r0.w + h1*r1.w + h2*r2.w + h3*r3.w;
            OMX[rbase[u] + c] = q;   // out has exactly the residuals layout
        }
    }
}

extern "C" void kernel_launch(void* const* d_in, const int* in_sizes, int n_in,
                              void* d_out, int out_size)
{
    const float* resid       = (const float*)d_in[0];
    const float* branch      = (const float*)d_in[1];
    const float* rmsw        = (const float*)d_in[2];
    const float* projW       = (const float*)d_in[3];
    const float* log_sigma   = (const float*)d_in[4];
    const float* pre_logits  = (const float*)d_in[5];
    const float* post_logits = (const float*)d_in[6];

    float* out_bi  = (float*)d_out;                                   // (B,T,D) first
    float* out_mix = (float*)d_out + (size_t)B_DIM * T_DIM * D_DIM;   // then (B*S,T,D)

    dim3 grid(B_DIM * T_DIM);
    dim3 block(256);
    ghc_kernel<<<grid, block>>>(resid, branch, rmsw, projW, log_sigma,
                                pre_logits, post_logits, out_bi, out_mix);
}

// round 2
// speedup vs baseline: 1.2669x; 1.2669x over previous
#include <cuda_runtime.h>
#include <cuda_bf16.h>

// GeometricHyperConnections — fused, HBM-bound.
// b=4, s=4, T=2048, d=2048, k=4 (fixed by setup_inputs).
// One CTA per (b,t) token; 256 threads.
// Pass 1 is stream-split (64 threads per stream -> 5 accumulators/thread)
// and stages residuals in SMEM; pass 2 mixes from SMEM. Register target <=64
// for 4 CTAs/SM.

#define T_DIM 2048
#define D_DIM 2048
#define D4    512         // D_DIM/4
#define B_DIM 4
#define S_DIM 4
#define K_DIM 4
#define TAU   0.05f
#define LOGM  (-1.3862943611198906f)   // -log(4)
#define RMSEPS 1e-6f

__global__ void __launch_bounds__(256, 4)
ghc_kernel(const float* __restrict__ resid,
           const float* __restrict__ branch,
           const float* __restrict__ rmsw,
           const float* __restrict__ projW,
           const float* __restrict__ log_sigma,
           const float* __restrict__ pre_logits,
           const float* __restrict__ post_logits,
           float* __restrict__ out_bi,     // (B,T,D)
           float* __restrict__ out_mix)    // (B*S,T,D)
{
    __shared__ float tile[S_DIM][D_DIM];   // staged residual rows (32 KB)
    __shared__ float red[8][5];            // per-warp partials
    __shared__ float coords[16];
    __shared__ float Hs[16];               // Hs[s*4+u]
    __shared__ float Hpre[4], Hpost[4];

    const int tid  = threadIdx.x;
    const int warp = tid >> 5, lane = tid & 31;
    const int m    = blockIdx.x;
    const int bi   = m >> 11;              // m / T_DIM
    const int t    = m & (T_DIM - 1);

    const float4* R4 = (const float4*)resid;
    const float4* W4 = (const float4*)rmsw;
    const float4* P4 = (const float4*)projW;

    size_t rbase[S_DIM];
#pragma unroll
    for (int si = 0; si < S_DIM; si++)
        rbase[si] = ((size_t)(bi * S_DIM + si) * T_DIM + t) * D4;

    // ---------------- Pass 1: stream-split stats + SMEM staging -----------
    {
        const int s = tid >> 6;            // stream owned by this thread
        const int g = tid & 63;            // lane within stream group
        const size_t rb = rbase[s];
        float4* tl4 = (float4*)tile[s];

        float ssq = 0.f, d0 = 0.f, d1 = 0.f, d2 = 0.f, d3 = 0.f;
#pragma unroll
        for (int i = 0; i < 8; i++) {
            const int c = g + 64 * i;
            const float4 r = __ldcs(&R4[rb + c]);
            tl4[c] = r;
            const float4 w  = W4[c];
            const float4 p0 = P4[0 * D4 + c];
            const float4 p1 = P4[1 * D4 + c];
            const float4 p2 = P4[2 * D4 + c];
            const float4 p3 = P4[3 * D4 + c];
            ssq += r.x*r.x + r.y*r.y + r.z*r.z + r.w*r.w;
            const float ax = r.x*w.x, ay = r.y*w.y, az = r.z*w.z, aw = r.w*w.w;
            d0 += ax*p0.x + ay*p0.y + az*p0.z + aw*p0.w;
            d1 += ax*p1.x + ay*p1.y + az*p1.z + aw*p1.w;
            d2 += ax*p2.x + ay*p2.y + az*p2.z + aw*p2.w;
            d3 += ax*p3.x + ay*p3.y + az*p3.z + aw*p3.w;
        }

        float vals[5] = {ssq, d0, d1, d2, d3};
#pragma unroll
        for (int v = 0; v < 5; v++) {
            float x = vals[v];
#pragma unroll
            for (int off = 16; off; off >>= 1)
                x += __shfl_xor_sync(0xffffffffu, x, off);
            vals[v] = x;
        }
        if (lane == 0) {
#pragma unroll
            for (int v = 0; v < 5; v++) red[warp][v] = vals[v];
        }
    }
    __syncthreads();

    // ---------------- Warp 0: coords, Sinkhorn, softmaxes -----------------
    if (warp == 0) {
        if (lane < 16) {
            // lane = si*4 + k ; group si spans warps 2si, 2si+1
            const int si = lane >> 2, k = lane & 3;
            const float dsum = red[2 * si][1 + k] + red[2 * si + 1][1 + k];
            const float ssq  = red[2 * si][0]     + red[2 * si + 1][0];
            const float scale = rsqrtf(ssq * (1.f / (float)D_DIM) + RMSEPS);
            coords[lane] = scale * dsum;
        }
        __syncwarp();
        if (lane < 16) {
            const int i = lane >> 2, jj = lane & 3;
            float ds = 0.f;
#pragma unroll
            for (int k = 0; k < K_DIM; k++) {
                const float df = coords[i * 4 + k] - coords[jj * 4 + k];
                ds += df * df;
            }
            const float sigma_sq = __expf(2.f * log_sigma[0]);
            const float Z = -ds / (2.f * sigma_sq * TAU);

            float u = 0.f, v = 0.f;
            const unsigned M = 0x0000ffffu;
#pragma unroll
            for (int it = 0; it < 10; it++) {
                // u_i = logm - lse_j(Z + v_j)   (within quad: xor 1,2)
                float t0 = Z + v;
                float mx = t0;
                mx = fmaxf(mx, __shfl_xor_sync(M, mx, 1));
                mx = fmaxf(mx, __shfl_xor_sync(M, mx, 2));
                float p = __expf(t0 - mx);
                p += __shfl_xor_sync(M, p, 1);
                p += __shfl_xor_sync(M, p, 2);
                u = LOGM - (mx + __logf(p));
                // v_j = logm - lse_i(Z + u_i)   (across quads: xor 4,8)
                float t1 = Z + u;
                mx = t1;
                mx = fmaxf(mx, __shfl_xor_sync(M, mx, 4));
                mx = fmaxf(mx, __shfl_xor_sync(M, mx, 8));
                p = __expf(t1 - mx);
                p += __shfl_xor_sync(M, p, 4);
                p += __shfl_xor_sync(M, p, 8);
                v = LOGM - (mx + __logf(p));
            }
            Hs[lane] = __expf(Z + u + v) * (float)S_DIM;
        }
        if (lane == 0) {
            float l[4], mx, e[4], sm;
#pragma unroll
            for (int i = 0; i < 4; i++) l[i] = pre_logits[i];
            mx = fmaxf(fmaxf(l[0], l[1]), fmaxf(l[2], l[3]));
            sm = 0.f;
#pragma unroll
            for (int i = 0; i < 4; i++) { e[i] = __expf(l[i] - mx); sm += e[i]; }
#pragma unroll
            for (int i = 0; i < 4; i++) Hpre[i] = e[i] / sm;
#pragma unroll
            for (int i = 0; i < 4; i++) l[i] = post_logits[i];
            mx = fmaxf(fmaxf(l[0], l[1]), fmaxf(l[2], l[3]));
            sm = 0.f;
#pragma unroll
            for (int i = 0; i < 4; i++) { e[i] = __expf(l[i] - mx); sm += e[i]; }
#pragma unroll
            for (int i = 0; i < 4; i++) Hpost[i] = e[i] / sm;
        }
    }
    __syncthreads();

    // ---------------- Pass 2: mixing + outputs (r from SMEM) --------------
    const float4* BO4 = (const float4*)branch;
    float4* OBI = (float4*)out_bi;
    float4* OMX = (float4*)out_mix;
    const size_t bbase = ((size_t)bi * T_DIM + t) * D4;

#pragma unroll
    for (int j = 0; j < 2; j++) {
        const int c = tid + j * 256;
        const float4 r0 = ((const float4*)tile[0])[c];
        const float4 r1 = ((const float4*)tile[1])[c];
        const float4 r2 = ((const float4*)tile[2])[c];
        const float4 r3 = ((const float4*)tile[3])[c];
        const float4 bo = __ldcs(&BO4[bbase + c]);

        {
            const float h0 = Hpre[0], h1 = Hpre[1], h2 = Hpre[2], h3 = Hpre[3];
            float4 o;
            o.x = h0*r0.x + h1*r1.x + h2*r2.x + h3*r3.x;
            o.y = h0*r0.y + h1*r1.y + h2*r2.y + h3*r3.y;
            o.z = h0*r0.z + h1*r1.z + h2*r2.z + h3*r3.z;
            o.w = h0*r0.w + h1*r1.w + h2*r2.w + h3*r3.w;
            __stcs(&OBI[bbase + c], o);
        }

#pragma unroll
        for (int u = 0; u < 4; u++) {
            const float h0 = Hs[0 * 4 + u], h1 = Hs[1 * 4 + u],
                        h2 = Hs[2 * 4 + u], h3 = Hs[3 * 4 + u], hb = Hpost[u];
            float4 q;
            q.x = hb*bo.x + h0*r0.x + h1*r1.x + h2*r2.x + h3*r3.x;
            q.y = hb*bo.y + h0*r0.y + h1*r1.y + h2*r2.y + h3*r3.y;
            q.z = hb*bo.z + h0*r0.z + h1*r1.z + h2*r2.z + h3*r3.z;
            q.w = hb*bo.w + h0*r0.w + h1*r1.w + h2*r2.w + h3*r3.w;
            __stcs(&OMX[rbase[u] + c], q);
        }
    }
}

extern "C" void kernel_launch(void* const* d_in, const int* in_sizes, int n_in,
                              void* d_out, int out_size)
{
    const float* resid       = (const float*)d_in[0];
    const float* branch      = (const float*)d_in[1];
    const float* rmsw        = (const float*)d_in[2];
    const float* projW       = (const float*)d_in[3];
    const float* log_sigma   = (const float*)d_in[4];
    const float* pre_logits  = (const float*)d_in[5];
    const float* post_logits = (const float*)d_in[6];

    float* out_bi  = (float*)d_out;                                   // (B,T,D) first
    float* out_mix = (float*)d_out + (size_t)B_DIM * T_DIM * D_DIM;   // then (B*S,T,D)

    dim3 grid(B_DIM * T_DIM);
    dim3 block(256);
    ghc_kernel<<<grid, block>>>(resid, branch, rmsw, projW, log_sigma,
                                pre_logits, post_logits, out_bi, out_mix);
}

// round 4
// speedup vs baseline: 1.3712x; 1.0823x over previous
#include <cuda_runtime.h>
#include <cuda_bf16.h>

// GeometricHyperConnections — fused, HBM-bound.
// b=4, s=4, T=2048, d=2048, k=4.
// One CTA per (b,t) token; 256 threads; ONE block barrier.
// Every warp redundantly computes the 4x4 Sinkhorn (no serial warp-0 section).

#define T_DIM 2048
#define D_DIM 2048
#define D4    512         // D_DIM/4
#define B_DIM 4
#define S_DIM 4
#define K_DIM 4
#define TAU   0.05f
#define LOGM  (-1.3862943611198906f)   // -log(4)
#define RMSEPS 1e-6f

__global__ void __launch_bounds__(256, 4)
ghc_kernel(const float* __restrict__ resid,
           const float* __restrict__ branch,
           const float* __restrict__ rmsw,
           const float* __restrict__ projW,
           const float* __restrict__ log_sigma,
           const float* __restrict__ pre_logits,
           const float* __restrict__ post_logits,
           float* __restrict__ out_bi,     // (B,T,D)
           float* __restrict__ out_mix)    // (B*S,T,D)
{
    __shared__ float tile[S_DIM][D_DIM];   // staged residual rows (32 KB)
    __shared__ float red[8][5];            // per-warp partials
    __shared__ float coords_w[8][16];      // per-warp private scratch
    __shared__ float Hs_w[8][16];          // per-warp H result

    const int tid  = threadIdx.x;
    const int warp = tid >> 5, lane = tid & 31;
    const int m    = blockIdx.x;
    const int bi   = m >> 11;              // m / T_DIM
    const int t    = m & (T_DIM - 1);

    const float4* R4 = (const float4*)resid;
    const float4* W4 = (const float4*)rmsw;
    const float4* P4 = (const float4*)projW;
    const float4* BO4 = (const float4*)branch;

    size_t rbase[S_DIM];
#pragma unroll
    for (int si = 0; si < S_DIM; si++)
        rbase[si] = ((size_t)(bi * S_DIM + si) * T_DIM + t) * D4;
    const size_t bbase = ((size_t)bi * T_DIM + t) * D4;

    // ---- Hpre / Hpost: every thread computes both tiny softmaxes ----------
    float hp[4], hq[4];
    {
        float l[4], mx, sm;
#pragma unroll
        for (int i = 0; i < 4; i++) l[i] = __ldg(&pre_logits[i]);
        mx = fmaxf(fmaxf(l[0], l[1]), fmaxf(l[2], l[3]));
        sm = 0.f;
#pragma unroll
        for (int i = 0; i < 4; i++) { hp[i] = __expf(l[i] - mx); sm += hp[i]; }
        sm = 1.f / sm;
#pragma unroll
        for (int i = 0; i < 4; i++) hp[i] *= sm;
#pragma unroll
        for (int i = 0; i < 4; i++) l[i] = __ldg(&post_logits[i]);
        mx = fmaxf(fmaxf(l[0], l[1]), fmaxf(l[2], l[3]));
        sm = 0.f;
#pragma unroll
        for (int i = 0; i < 4; i++) { hq[i] = __expf(l[i] - mx); sm += hq[i]; }
        sm = 1.f / sm;
#pragma unroll
        for (int i = 0; i < 4; i++) hq[i] *= sm;
    }

    // ---------------- Pass 1: stream-split stats + SMEM staging -----------
    {
        const int s = tid >> 6;            // stream owned by this thread
        const int g = tid & 63;            // lane within stream group
        const size_t rb = rbase[s];
        float4* tl4 = (float4*)tile[s];

        float ssq = 0.f, d0 = 0.f, d1 = 0.f, d2 = 0.f, d3 = 0.f;
#pragma unroll
        for (int i = 0; i < 8; i++) {
            const int c = g + 64 * i;
            const float4 r = __ldcs(&R4[rb + c]);
            tl4[c] = r;
            const float4 w  = W4[c];
            const float4 p0 = P4[0 * D4 + c];
            const float4 p1 = P4[1 * D4 + c];
            const float4 p2 = P4[2 * D4 + c];
            const float4 p3 = P4[3 * D4 + c];
            ssq += r.x*r.x + r.y*r.y + r.z*r.z + r.w*r.w;
            const float ax = r.x*w.x, ay = r.y*w.y, az = r.z*w.z, aw = r.w*w.w;
            d0 += ax*p0.x + ay*p0.y + az*p0.z + aw*p0.w;
            d1 += ax*p1.x + ay*p1.y + az*p1.z + aw*p1.w;
            d2 += ax*p2.x + ay*p2.y + az*p2.z + aw*p2.w;
            d3 += ax*p3.x + ay*p3.y + az*p3.z + aw*p3.w;
        }

        float vals[5] = {ssq, d0, d1, d2, d3};
#pragma unroll
        for (int v = 0; v < 5; v++) {
            float x = vals[v];
#pragma unroll
            for (int off = 16; off; off >>= 1)
                x += __shfl_xor_sync(0xffffffffu, x, off);
            vals[v] = x;
        }
        if (lane == 0) {
#pragma unroll
            for (int v = 0; v < 5; v++) red[warp][v] = vals[v];
        }
    }

    // Prefetch branch_output while partials settle (overlaps barrier).
    const float4 bo0 = __ldcs(&BO4[bbase + tid]);
    const float4 bo1 = __ldcs(&BO4[bbase + tid + 256]);

    __syncthreads();   // the ONLY block barrier

    float4* OBI = (float4*)out_bi;
    float4* OMX = (float4*)out_mix;

    // ---- branch_input first: only needs Hpre; stores drain during Sinkhorn
#pragma unroll
    for (int j = 0; j < 2; j++) {
        const int c = tid + j * 256;
        const float4 r0 = ((const float4*)tile[0])[c];
        const float4 r1 = ((const float4*)tile[1])[c];
        const float4 r2 = ((const float4*)tile[2])[c];
        const float4 r3 = ((const float4*)tile[3])[c];
        float4 o;
        o.x = hp[0]*r0.x + hp[1]*r1.x + hp[2]*r2.x + hp[3]*r3.x;
        o.y = hp[0]*r0.y + hp[1]*r1.y + hp[2]*r2.y + hp[3]*r3.y;
        o.z = hp[0]*r0.z + hp[1]*r1.z + hp[2]*r2.z + hp[3]*r3.z;
        o.w = hp[0]*r0.w + hp[1]*r1.w + hp[2]*r2.w + hp[3]*r3.w;
        __stcs(&OBI[bbase + c], o);
    }

    // ---- Every warp: coords + Sinkhorn (lanes 0-15), fully parallel -------
    if (lane < 16) {
        const int si = lane >> 2, k = lane & 3;
        const float dsum = red[2 * si][1 + k] + red[2 * si + 1][1 + k];
        const float ssq  = red[2 * si][0]     + red[2 * si + 1][0];
        const float scale = rsqrtf(ssq * (1.f / (float)D_DIM) + RMSEPS);
        coords_w[warp][lane] = scale * dsum;
    }
    __syncwarp();
    if (lane < 16) {
        const int i = lane >> 2, jj = lane & 3;
        float ds = 0.f;
#pragma unroll
        for (int k = 0; k < K_DIM; k++) {
            const float df = coords_w[warp][i * 4 + k] - coords_w[warp][jj * 4 + k];
            ds += df * df;
        }
        const float sigma_sq = __expf(2.f * __ldg(log_sigma));
        const float Z = -ds / (2.f * sigma_sq * TAU);

        float u = 0.f, v = 0.f;
        const unsigned M = 0x0000ffffu;
#pragma unroll
        for (int it = 0; it < 10; it++) {
            float t0 = Z + v;
            float mx = t0;
            mx = fmaxf(mx, __shfl_xor_sync(M, mx, 1));
            mx = fmaxf(mx, __shfl_xor_sync(M, mx, 2));
            float p = __expf(t0 - mx);
            p += __shfl_xor_sync(M, p, 1);
            p += __shfl_xor_sync(M, p, 2);
            u = LOGM - (mx + __logf(p));
            float t1 = Z + u;
            mx = t1;
            mx = fmaxf(mx, __shfl_xor_sync(M, mx, 4));
            mx = fmaxf(mx, __shfl_xor_sync(M, mx, 8));
            p = __expf(t1 - mx);
            p += __shfl_xor_sync(M, p, 4);
            p += __shfl_xor_sync(M, p, 8);
            v = LOGM - (mx + __logf(p));
        }
        Hs_w[warp][lane] = __expf(Z + u + v) * (float)S_DIM;
    }
    __syncwarp();

    // ---------------- Mixed outputs ----------------------------------------
    const float* H = Hs_w[warp];
#pragma unroll
    for (int j = 0; j < 2; j++) {
        const int c = tid + j * 256;
        const float4 r0 = ((const float4*)tile[0])[c];
        const float4 r1 = ((const float4*)tile[1])[c];
        const float4 r2 = ((const float4*)tile[2])[c];
        const float4 r3 = ((const float4*)tile[3])[c];
        const float4 bo = (j == 0) ? bo0 : bo1;

#pragma unroll
        for (int u = 0; u < 4; u++) {
            const float h0 = H[0 * 4 + u], h1 = H[1 * 4 + u],
                        h2 = H[2 * 4 + u], h3 = H[3 * 4 + u], hb = hq[u];
            float4 q;
            q.x = hb*bo.x + h0*r0.x + h1*r1.x + h2*r2.x + h3*r3.x;
            q.y = hb*bo.y + h0*r0.y + h1*r1.y + h2*r2.y + h3*r3.y;
            q.z = hb*bo.z + h0*r0.z + h1*r1.z + h2*r2.z + h3*r3.z;
            q.w = hb*bo.w + h0*r0.w + h1*r1.w + h2*r2.w + h3*r3.w;
            __stcs(&OMX[rbase[u] + c], q);
        }
    }
}

extern "C" void kernel_launch(void* const* d_in, const int* in_sizes, int n_in,
                              void* d_out, int out_size)
{
    const float* resid       = (const float*)d_in[0];
    const float* branch      = (const float*)d_in[1];
    const float* rmsw        = (const float*)d_in[2];
    const float* projW       = (const float*)d_in[3];
    const float* log_sigma   = (const float*)d_in[4];
    const float* pre_logits  = (const float*)d_in[5];
    const float* post_logits = (const float*)d_in[6];

    float* out_bi  = (float*)d_out;                                   // (B,T,D) first
    float* out_mix = (float*)d_out + (size_t)B_DIM * T_DIM * D_DIM;   // then (B*S,T,D)

    dim3 grid(B_DIM * T_DIM);
    dim3 block(256);
    ghc_kernel<<<grid, block>>>(resid, branch, rmsw, projW, log_sigma,
                                pre_logits, post_logits, out_bi, out_mix);
}

// round 5
// speedup vs baseline: 1.4736x; 1.0747x over previous
#include <cuda_runtime.h>
#include <cuda_bf16.h>

// GeometricHyperConnections — fused, HBM-bound.
// b=4, s=4, T=2048, d=2048, k=4.
// One CTA per (b,t) token; 256 threads; ONE block barrier.
// Pass 1: all-streams-per-thread (weights loaded ONCE per column -> 4x fewer
// broadcast weight loads, the former L1 bottleneck). 20 accumulators/thread.
// Every warp redundantly computes the 4x4 Sinkhorn (no serial section).

#define T_DIM 2048
#define D_DIM 2048
#define D4    512         // D_DIM/4
#define B_DIM 4
#define S_DIM 4
#define K_DIM 4
#define TAU   0.05f
#define LOGM  (-1.3862943611198906f)   // -log(4)
#define RMSEPS 1e-6f

__global__ void __launch_bounds__(256, 4)
ghc_kernel(const float* __restrict__ resid,
           const float* __restrict__ branch,
           const float* __restrict__ rmsw,
           const float* __restrict__ projW,
           const float* __restrict__ log_sigma,
           const float* __restrict__ pre_logits,
           const float* __restrict__ post_logits,
           float* __restrict__ out_bi,     // (B,T,D)
           float* __restrict__ out_mix)    // (B*S,T,D)
{
    __shared__ float tile[S_DIM][D_DIM];   // staged residual rows (32 KB)
    __shared__ float red[8][20];           // per-warp partials
    __shared__ float coords_w[8][16];      // per-warp private scratch
    __shared__ float Hs_w[8][16];          // per-warp H result

    const int tid  = threadIdx.x;
    const int warp = tid >> 5, lane = tid & 31;
    const int m    = blockIdx.x;
    const int bi   = m >> 11;              // m / T_DIM
    const int t    = m & (T_DIM - 1);

    const float4* R4  = (const float4*)resid;
    const float4* W4  = (const float4*)rmsw;
    const float4* P4  = (const float4*)projW;
    const float4* BO4 = (const float4*)branch;

    // 32-bit float4 offsets (max 16M, fits easily)
    unsigned rbase[S_DIM];
#pragma unroll
    for (int si = 0; si < S_DIM; si++)
        rbase[si] = (unsigned)((bi * S_DIM + si) * T_DIM + t) * D4;
    const unsigned bbase = (unsigned)(bi * T_DIM + t) * D4;

    // ---- Hpre / Hpost: every thread computes both tiny softmaxes ----------
    float hp[4], hq[4];
    {
        float l[4], mx, sm;
#pragma unroll
        for (int i = 0; i < 4; i++) l[i] = __ldg(&pre_logits[i]);
        mx = fmaxf(fmaxf(l[0], l[1]), fmaxf(l[2], l[3]));
        sm = 0.f;
#pragma unroll
        for (int i = 0; i < 4; i++) { hp[i] = __expf(l[i] - mx); sm += hp[i]; }
        sm = 1.f / sm;
#pragma unroll
        for (int i = 0; i < 4; i++) hp[i] *= sm;
#pragma unroll
        for (int i = 0; i < 4; i++) l[i] = __ldg(&post_logits[i]);
        mx = fmaxf(fmaxf(l[0], l[1]), fmaxf(l[2], l[3]));
        sm = 0.f;
#pragma unroll
        for (int i = 0; i < 4; i++) { hq[i] = __expf(l[i] - mx); sm += hq[i]; }
        sm = 1.f / sm;
#pragma unroll
        for (int i = 0; i < 4; i++) hq[i] *= sm;
    }

    // ---------------- Pass 1: all streams per thread + SMEM staging --------
    // acc[0..3] = sumsq[s]; acc[4 + s*4 + k] = dot[s][k]
    float acc[20];
#pragma unroll
    for (int v = 0; v < 20; v++) acc[v] = 0.f;

#pragma unroll
    for (int j = 0; j < 2; j++) {
        const int c = tid + j * 256;
        const float4 w  = W4[c];
        const float4 p0 = P4[0 * D4 + c];
        const float4 p1 = P4[1 * D4 + c];
        const float4 p2 = P4[2 * D4 + c];
        const float4 p3 = P4[3 * D4 + c];
#pragma unroll
        for (int s = 0; s < S_DIM; s++) {
            const float4 r = __ldcs(&R4[rbase[s] + c]);
            ((float4*)tile[s])[c] = r;
            acc[s] += r.x*r.x + r.y*r.y + r.z*r.z + r.w*r.w;
            const float ax = r.x*w.x, ay = r.y*w.y, az = r.z*w.z, aw = r.w*w.w;
            acc[4 + s*4 + 0] += ax*p0.x + ay*p0.y + az*p0.z + aw*p0.w;
            acc[4 + s*4 + 1] += ax*p1.x + ay*p1.y + az*p1.z + aw*p1.w;
            acc[4 + s*4 + 2] += ax*p2.x + ay*p2.y + az*p2.z + aw*p2.w;
            acc[4 + s*4 + 3] += ax*p3.x + ay*p3.y + az*p3.z + aw*p3.w;
        }
    }

#pragma unroll
    for (int v = 0; v < 20; v++) {
        float x = acc[v];
#pragma unroll
        for (int off = 16; off; off >>= 1)
            x += __shfl_xor_sync(0xffffffffu, x, off);
        acc[v] = x;
    }
    if (lane == 0) {
#pragma unroll
        for (int v = 0; v < 20; v++) red[warp][v] = acc[v];
    }

    // Prefetch branch_output while partials settle (overlaps barrier).
    const float4 bo0 = __ldcs(&BO4[bbase + tid]);
    const float4 bo1 = __ldcs(&BO4[bbase + tid + 256]);

    __syncthreads();   // the ONLY block barrier

    float4* OBI = (float4*)out_bi;
    float4* OMX = (float4*)out_mix;

    // ---- branch_input first: only needs Hpre; stores drain during Sinkhorn
#pragma unroll
    for (int j = 0; j < 2; j++) {
        const int c = tid + j * 256;
        const float4 r0 = ((const float4*)tile[0])[c];
        const float4 r1 = ((const float4*)tile[1])[c];
        const float4 r2 = ((const float4*)tile[2])[c];
        const float4 r3 = ((const float4*)tile[3])[c];
        float4 o;
        o.x = hp[0]*r0.x + hp[1]*r1.x + hp[2]*r2.x + hp[3]*r3.x;
        o.y = hp[0]*r0.y + hp[1]*r1.y + hp[2]*r2.y + hp[3]*r3.y;
        o.z = hp[0]*r0.z + hp[1]*r1.z + hp[2]*r2.z + hp[3]*r3.z;
        o.w = hp[0]*r0.w + hp[1]*r1.w + hp[2]*r2.w + hp[3]*r3.w;
        __stcs(&OBI[bbase + c], o);
    }

    // ---- Every warp: coords + Sinkhorn (lanes 0-15), fully parallel -------
    if (lane < 16) {
        const int si = lane >> 2;
        float ssq = 0.f, dsum = 0.f;
#pragma unroll
        for (int w = 0; w < 8; w++) {
            ssq  += red[w][si];
            dsum += red[w][4 + lane];
        }
        const float scale = rsqrtf(ssq * (1.f / (float)D_DIM) + RMSEPS);
        coords_w[warp][lane] = scale * dsum;
    }
    __syncwarp();
    if (lane < 16) {
        const int i = lane >> 2, jj = lane & 3;
        float ds = 0.f;
#pragma unroll
        for (int k = 0; k < K_DIM; k++) {
            const float df = coords_w[warp][i * 4 + k] - coords_w[warp][jj * 4 + k];
            ds += df * df;
        }
        const float sigma_sq = __expf(2.f * __ldg(log_sigma));
        const float Z = -ds / (2.f * sigma_sq * TAU);

        float u = 0.f, v = 0.f;
        const unsigned M = 0x0000ffffu;
#pragma unroll
        for (int it = 0; it < 10; it++) {
            float t0 = Z + v;
            float mx = t0;
            mx = fmaxf(mx, __shfl_xor_sync(M, mx, 1));
            mx = fmaxf(mx, __shfl_xor_sync(M, mx, 2));
            float p = __expf(t0 - mx);
            p += __shfl_xor_sync(M, p, 1);
            p += __shfl_xor_sync(M, p, 2);
            u = LOGM - (mx + __logf(p));
            float t1 = Z + u;
            mx = t1;
            mx = fmaxf(mx, __shfl_xor_sync(M, mx, 4));
            mx = fmaxf(mx, __shfl_xor_sync(M, mx, 8));
            p = __expf(t1 - mx);
            p += __shfl_xor_sync(M, p, 4);
            p += __shfl_xor_sync(M, p, 8);
            v = LOGM - (mx + __logf(p));
        }
        Hs_w[warp][lane] = __expf(Z + u + v) * (float)S_DIM;
    }
    __syncwarp();

    // ---------------- Mixed outputs ----------------------------------------
    const float* H = Hs_w[warp];
#pragma unroll
    for (int j = 0; j < 2; j++) {
        const int c = tid + j * 256;
        const float4 r0 = ((const float4*)tile[0])[c];
        const float4 r1 = ((const float4*)tile[1])[c];
        const float4 r2 = ((const float4*)tile[2])[c];
        const float4 r3 = ((const float4*)tile[3])[c];
        const float4 bo = (j == 0) ? bo0 : bo1;

#pragma unroll
        for (int u = 0; u < 4; u++) {
            const float h0 = H[0 * 4 + u], h1 = H[1 * 4 + u],
                        h2 = H[2 * 4 + u], h3 = H[3 * 4 + u], hb = hq[u];
            float4 q;
            q.x = hb*bo.x + h0*r0.x + h1*r1.x + h2*r2.x + h3*r3.x;
            q.y = hb*bo.y + h0*r0.y + h1*r1.y + h2*r2.y + h3*r3.y;
            q.z = hb*bo.z + h0*r0.z + h1*r1.z + h2*r2.z + h3*r3.z;
            q.w = hb*bo.w + h0*r0.w + h1*r1.w + h2*r2.w + h3*r3.w;
            __stcs(&OMX[rbase[u] + c], q);
        }
    }
}

extern "C" void kernel_launch(void* const* d_in, const int* in_sizes, int n_in,
                              void* d_out, int out_size)
{
    const float* resid       = (const float*)d_in[0];
    const float* branch      = (const float*)d_in[1];
    const float* rmsw        = (const float*)d_in[2];
    const float* projW       = (const float*)d_in[3];
    const float* log_sigma   = (const float*)d_in[4];
    const float* pre_logits  = (const float*)d_in[5];
    const float* post_logits = (const float*)d_in[6];

    float* out_bi  = (float*)d_out;                                   // (B,T,D) first
    float* out_mix = (float*)d_out + (size_t)B_DIM * T_DIM * D_DIM;   // then (B*S,T,D)

    dim3 grid(B_DIM * T_DIM);
    dim3 block(256);
    ghc_kernel<<<grid, block>>>(resid, branch, rmsw, projW, log_sigma,
                                pre_logits, post_logits, out_bi, out_mix);
}